// round 5
// baseline (speedup 1.0000x reference)
#include <cuda_runtime.h>

// SwinV2 shifted-window attention, B=16, H=W=64, C=256, heads=8, hd=32,
// window 8x8, shift 4x4  ->  1024 windows x 64 tokens.
//
// Round 5: attention moved to tensor cores. QK^T in 3xTF32 (accurate logits),
// softmax on fragments, PV in tf32. One warp per (window, head). Q/K hi+lo
// and V tf32 produced directly by the QKV epilogue.

#define NWIN   1024
#define NTOK   64
#define CDIM   256
#define NHEAD  8
#define HD     32

typedef unsigned long long u64;

// -------- scratch (device globals; no allocation) --------
__device__ unsigned g_qh [NWIN * NHEAD * NTOK * HD];  // q hi tf32 bits
__device__ unsigned g_ql [NWIN * NHEAD * NTOK * HD];  // q lo tf32 bits
__device__ unsigned g_kh [NWIN * NHEAD * NTOK * HD];  // k hi tf32 bits
__device__ unsigned g_kl [NWIN * NHEAD * NTOK * HD];  // k lo tf32 bits
__device__ unsigned g_v  [NWIN * NHEAD * NTOK * HD];  // v tf32 bits
__device__ unsigned g_ao [NWIN * NTOK * CDIM];        // attn out tf32 bits
__device__ unsigned g_xtf[16 * 64 * 64 * CDIM];       // x tf32 bits
__device__ unsigned g_wtf[4 * CDIM * CDIM];           // weights tf32 bits
__device__ float    g_bias16[NHEAD * 225];
__device__ float    g_scale[NHEAD];

// -------- helpers --------
__device__ __forceinline__ unsigned f2tf(float f) {
    unsigned u;
    asm("cvt.rna.tf32.f32 %0, %1;" : "=r"(u) : "f"(f));
    return u;
}
__device__ __forceinline__ void mma8(float* c, const unsigned* a, const unsigned* b) {
    asm volatile("mma.sync.aligned.m16n8k8.row.col.f32.tf32.tf32.f32 "
                 "{%0,%1,%2,%3},{%4,%5,%6,%7},{%8,%9},{%0,%1,%2,%3};"
                 : "+f"(c[0]), "+f"(c[1]), "+f"(c[2]), "+f"(c[3])
                 : "r"(a[0]), "r"(a[1]), "r"(a[2]), "r"(a[3]),
                   "r"(b[0]), "r"(b[1]));
}
__device__ __forceinline__ void cp16(unsigned dst, const void* src) {
    asm volatile("cp.async.cg.shared.global [%0], [%1], 16;" :: "r"(dst), "l"(src));
}
__device__ __forceinline__ void cp_commit() {
    asm volatile("cp.async.commit_group;");
}
template<int N> __device__ __forceinline__ void cp_wait() {
    asm volatile("cp.async.wait_group %0;" :: "n"(N));
}

// -------- GEMM smem geometry --------
#define XCH   36
#define WST   264
#define XBUF  (128 * XCH)
#define WBUF  (32 * WST)
#define NSTG  3
#define G_SMEM ((NSTG * (XBUF + WBUF) + 128) * 4)

// ============================================================
// Kernel 0: continuous-position-bias MLP
// ============================================================
__global__ void swin_bias_kernel(const float* __restrict__ ls,
                                 const float* __restrict__ w1,
                                 const float* __restrict__ b1,
                                 const float* __restrict__ w2)
{
    __shared__ float part[16][8];
    const int t   = blockIdx.x;
    const int i   = t / 15;
    const int j   = t % 15;
    const int tid = threadIdx.x;
    const int warp = tid >> 5;
    const int lane = tid & 31;

    float rh = (float)(i - 7) * (8.0f / 7.0f);
    float rw = (float)(j - 7) * (8.0f / 7.0f);
    rh = copysignf(log2f(fabsf(rh) + 1.0f) * (1.0f / 3.0f), rh);
    rw = copysignf(log2f(fabsf(rw) + 1.0f) * (1.0f / 3.0f), rw);

    float hv = fmaxf(0.0f, rh * w1[tid] + rw * w1[512 + tid] + b1[tid]);

    float p[8];
#pragma unroll
    for (int h = 0; h < 8; ++h) p[h] = hv * w2[tid * 8 + h];
#pragma unroll
    for (int off = 16; off; off >>= 1)
#pragma unroll
        for (int h = 0; h < 8; ++h) p[h] += __shfl_xor_sync(0xffffffffu, p[h], off);
    if (lane == 0)
#pragma unroll
        for (int h = 0; h < 8; ++h) part[warp][h] = p[h];
    __syncthreads();

    if (tid < 8) {
        float s = 0.0f;
#pragma unroll
        for (int g = 0; g < 16; ++g) s += part[g][tid];
        g_bias16[tid * 225 + t] = 16.0f / (1.0f + expf(-s));
    }
    if (blockIdx.x == 0 && tid < 8)
        g_scale[tid] = expf(fminf(ls[tid], 4.6051701860f));
}

// ============================================================
// Kernel 0b: convert x and weights to tf32 bits (once)
// ============================================================
__global__ void swin_cvt_kernel(const float* __restrict__ x,
                                const float* __restrict__ Wq,
                                const float* __restrict__ Wk,
                                const float* __restrict__ Wv,
                                const float* __restrict__ Wo)
{
    const int blk = blockIdx.x;
    const int tid = threadIdx.x;
    if (blk < 16384) {
        int i4 = blk * 256 + tid;
        float4 v = ((const float4*)x)[i4];
        ((uint4*)g_xtf)[i4] = make_uint4(f2tf(v.x), f2tf(v.y), f2tf(v.z), f2tf(v.w));
    } else {
        int r  = blk - 16384;
        int m  = r >> 6;
        int i4 = (r & 63) * 256 + tid;
        const float* W = (m == 0) ? Wq : (m == 1) ? Wk : (m == 2) ? Wv : Wo;
        float4 v = ((const float4*)W)[i4];
        ((uint4*)(g_wtf + m * 65536))[i4] =
            make_uint4(f2tf(v.x), f2tf(v.y), f2tf(v.z), f2tf(v.w));
    }
}

// ============================================================
// Kernel 1: QKV projection (tf32 MMA, cp.async 3-stage)
// epilogue stores q,k as hi/lo tf32 splits and v as tf32 bits.
// ============================================================
__global__ void __launch_bounds__(512)
swin_qkv_kernel(const float* __restrict__ bq,
                const float* __restrict__ bk,
                const float* __restrict__ bv)
{
    extern __shared__ unsigned sm[];
    unsigned* Xs = sm;
    unsigned* Wt = sm + NSTG * XBUF;
    unsigned* rowbase = sm + NSTG * (XBUF + WBUF);
    const unsigned smem_base = (unsigned)__cvta_generic_to_shared(sm);

    const int bw   = blockIdx.x;
    const int tid  = threadIdx.x;
    const int warp = tid >> 5;
    const int lane = tid & 31;
    const int g    = lane >> 2;
    const int t    = lane & 3;
    const int mw   = warp >> 2;
    const int nw   = warp & 3;

    if (tid < 128) {
        int wv = bw * 2 + (tid >> 6);
        int b = wv >> 6, wy = (wv >> 3) & 7, wx = wv & 7;
        int tok = tid & 63;
        int sy = ((wy << 3) + (tok >> 3) + 4) & 63;
        int sx = ((wx << 3) + (tok & 7) + 4) & 63;
        rowbase[tid] = ((((b << 6) | sy) << 6) | sx) << 8;
    }
    __syncthreads();

    const int arow  = tid >> 3;
    const int apart = tid & 7;
    const unsigned rb0 = rowbase[arow];
    const unsigned rb1 = rowbase[arow + 64];
    const int bkk   = tid >> 6;
    const int bpart = tid & 63;

#define LOAD_A(kc, st) do {                                                    \
        unsigned d0 = smem_base + (((st) * XBUF + arow * XCH + apart * 4) << 2); \
        cp16(d0, g_xtf + rb0 + (kc) * 32 + apart * 4);                          \
        unsigned d1 = smem_base + (((st) * XBUF + (arow + 64) * XCH + apart * 4) << 2); \
        cp16(d1, g_xtf + rb1 + (kc) * 32 + apart * 4);                          \
    } while (0)

#define LOAD_B(W, kc, st) do {                                                 \
        _Pragma("unroll")                                                      \
        for (int jj = 0; jj < 4; ++jj) {                                       \
            int kk = bkk + jj * 8;                                             \
            unsigned d = smem_base +                                           \
                ((NSTG * XBUF + (st) * WBUF + kk * WST + bpart * 4) << 2);     \
            cp16(d, (W) + (((kc) * 32 + kk) << 8) + bpart * 4);                \
        }                                                                      \
    } while (0)

    const float* Bm[3] = {bq, bk, bv};

#pragma unroll 1
    for (int m = 0; m < 3; ++m) {
        const unsigned* W = g_wtf + m * 65536;
        float acc[2][8][4];
#pragma unroll
        for (int mt = 0; mt < 2; ++mt)
#pragma unroll
            for (int nt = 0; nt < 8; ++nt)
#pragma unroll
                for (int q = 0; q < 4; ++q) acc[mt][nt][q] = 0.0f;

        LOAD_A(0, 0); LOAD_B(W, 0, 0); cp_commit();
        LOAD_A(1, 1); LOAD_B(W, 1, 1); cp_commit();

#pragma unroll 1
        for (int kc = 0; kc < 8; ++kc) {
            if (kc + 2 < 8) {
                int st = (kc + 2) % 3;
                LOAD_A(kc + 2, st); LOAD_B(W, kc + 2, st);
            }
            cp_commit();
            cp_wait<2>();
            __syncthreads();

            const unsigned* XsS = Xs + (kc % 3) * XBUF;
            const unsigned* WtS = Wt + (kc % 3) * WBUF;
#pragma unroll
            for (int ks = 0; ks < 4; ++ks) {
                const int kb = ks * 8;
                unsigned a[2][4];
#pragma unroll
                for (int mt = 0; mt < 2; ++mt) {
                    const unsigned* ar = XsS + (mw * 32 + mt * 16 + g) * XCH + kb + t;
                    a[mt][0] = ar[0];
                    a[mt][1] = ar[8 * XCH];
                    a[mt][2] = ar[4];
                    a[mt][3] = ar[8 * XCH + 4];
                }
                unsigned bf[8][2];
#pragma unroll
                for (int nt = 0; nt < 8; ++nt) {
                    const unsigned* br = WtS + (kb + t) * WST + nw * 64 + nt * 8 + g;
                    bf[nt][0] = br[0];
                    bf[nt][1] = br[4 * WST];
                }
#pragma unroll
                for (int mt = 0; mt < 2; ++mt)
#pragma unroll
                    for (int nt = 0; nt < 8; ++nt)
                        mma8(acc[mt][nt], a[mt], bf[nt]);
            }
            __syncthreads();
        }

        float2 bb[8];
#pragma unroll
        for (int nt = 0; nt < 8; ++nt)
            bb[nt] = *(const float2*)(Bm[m] + nw * 64 + nt * 8 + 2 * t);
#pragma unroll
        for (int mt = 0; mt < 2; ++mt)
#pragma unroll
            for (int nt = 0; nt < 8; ++nt) {
                acc[mt][nt][0] += bb[nt].x;  acc[mt][nt][1] += bb[nt].y;
                acc[mt][nt][2] += bb[nt].x;  acc[mt][nt][3] += bb[nt].y;
            }

        if (m < 2) {
#pragma unroll
            for (int mt = 0; mt < 2; ++mt)
#pragma unroll
                for (int rh = 0; rh < 2; ++rh)
#pragma unroll
                    for (int hh = 0; hh < 2; ++hh) {
                        float s = 0.0f;
#pragma unroll
                        for (int k2 = 0; k2 < 4; ++k2) {
                            int nt = hh * 4 + k2;
                            s += acc[mt][nt][rh * 2]     * acc[mt][nt][rh * 2]
                               + acc[mt][nt][rh * 2 + 1] * acc[mt][nt][rh * 2 + 1];
                        }
                        s += __shfl_xor_sync(0xffffffffu, s, 1);
                        s += __shfl_xor_sync(0xffffffffu, s, 2);
                        float inv = 1.0f / fmaxf(sqrtf(s), 1e-12f);
#pragma unroll
                        for (int k2 = 0; k2 < 4; ++k2) {
                            int nt = hh * 4 + k2;
                            acc[mt][nt][rh * 2]     *= inv;
                            acc[mt][nt][rh * 2 + 1] *= inv;
                        }
                    }
        }

#pragma unroll
        for (int mt = 0; mt < 2; ++mt)
#pragma unroll
            for (int rh = 0; rh < 2; ++rh)
#pragma unroll
                for (int nt = 0; nt < 8; ++nt) {
                    int n    = mw * 32 + mt * 16 + rh * 8 + g;
                    int win  = bw * 2 + (n >> 6);
                    int tok  = n & 63;
                    int col  = nw * 64 + nt * 8 + 2 * t;
                    int head = col >> 5;
                    int d    = col & 31;
                    int off  = (((win << 3) | head) << 11) + (tok << 5) + d;
                    float vx = acc[mt][nt][rh * 2];
                    float vy = acc[mt][nt][rh * 2 + 1];
                    if (m == 2) {
                        *(uint2*)(g_v + off) = make_uint2(f2tf(vx), f2tf(vy));
                    } else {
                        unsigned hx = f2tf(vx), hy = f2tf(vy);
                        unsigned lx = f2tf(vx - __uint_as_float(hx));
                        unsigned ly = f2tf(vy - __uint_as_float(hy));
                        if (m == 0) {
                            *(uint2*)(g_qh + off) = make_uint2(hx, hy);
                            *(uint2*)(g_ql + off) = make_uint2(lx, ly);
                        } else {
                            *(uint2*)(g_kh + off) = make_uint2(hx, hy);
                            *(uint2*)(g_kl + off) = make_uint2(lx, ly);
                        }
                    }
                }
    }
#undef LOAD_A
#undef LOAD_B
}

// ============================================================
// Kernel 2: MMA attention. grid 1024, 256 threads; warp = head.
// QK^T 3xTF32 -> fragment softmax -> PV tf32 (P staged via smem).
// ============================================================
__global__ void __launch_bounds__(256)
swin_attn_kernel()
{
    __shared__ unsigned ps[NHEAD][16 * 68];   // P tiles, tf32 bits
    __shared__ float    bs[NHEAD][226];

    const int w    = blockIdx.x;
    const int tid  = threadIdx.x;
    const int h    = tid >> 5;
    const int lane = tid & 31;
    const int g    = lane >> 2;
    const int t    = lane & 3;

    for (int i = lane; i < 225; i += 32) bs[h][i] = g_bias16[h * 225 + i];
    const float sc = g_scale[h];

    const int base = ((w << 3) | h) << 11;
    const unsigned* qh = g_qh + base;
    const unsigned* ql = g_ql + base;
    const unsigned* kh = g_kh + base;
    const unsigned* kl = g_kl + base;
    const unsigned* vv = g_v  + base;
    unsigned* psw = ps[h];

    const int wy = (w >> 3) & 7, wx = w & 7;
    const bool mhb = (wy == 7), mwb = (wx == 7);
    __syncwarp();

#pragma unroll 1
    for (int mt = 0; mt < 4; ++mt) {
        const int r0 = mt * 16 + g;
        const int r1 = r0 + 8;

        // Q fragments (hi + lo)
        unsigned aqh[4][4], aql[4][4];
#pragma unroll
        for (int ks = 0; ks < 4; ++ks) {
            int c0 = ks * 8 + t;
            aqh[ks][0] = qh[r0 * 32 + c0];     aqh[ks][1] = qh[r1 * 32 + c0];
            aqh[ks][2] = qh[r0 * 32 + c0 + 4]; aqh[ks][3] = qh[r1 * 32 + c0 + 4];
            aql[ks][0] = ql[r0 * 32 + c0];     aql[ks][1] = ql[r1 * 32 + c0];
            aql[ks][2] = ql[r0 * 32 + c0 + 4]; aql[ks][3] = ql[r1 * 32 + c0 + 4];
        }

        float cc[8][4];
#pragma unroll
        for (int nt = 0; nt < 8; ++nt)
#pragma unroll
            for (int q = 0; q < 4; ++q) cc[nt][q] = 0.0f;

#pragma unroll
        for (int nt = 0; nt < 8; ++nt) {
#pragma unroll
            for (int ks = 0; ks < 4; ++ks) {
                int ca = (nt * 8 + g) * 32 + ks * 8 + t;
                unsigned bh[2] = { kh[ca], kh[ca + 4] };
                unsigned bl[2] = { kl[ca], kl[ca + 4] };
                mma8(cc[nt], aqh[ks], bh);
                mma8(cc[nt], aql[ks], bh);
                mma8(cc[nt], aqh[ks], bl);
            }
        }

        // bias + mask
        const int ty0 = r0 >> 3, tx0 = r0 & 7;
        const int ty1 = r1 >> 3, tx1 = r1 & 7;
#pragma unroll
        for (int nt = 0; nt < 8; ++nt)
#pragma unroll
            for (int q = 0; q < 4; ++q) {
                int m  = nt * 8 + 2 * t + (q & 1);
                int my = m >> 3, mxc = m & 7;
                int ty = (q < 2) ? ty0 : ty1;
                int tx = (q < 2) ? tx0 : tx1;
                float v = cc[nt][q] * sc + bs[h][(ty - my + 7) * 15 + (tx - mxc + 7)];
                if (mhb && ((ty < 4) != (my < 4)))   v -= 100.0f;
                if (mwb && ((tx < 4) != (mxc < 4)))  v -= 100.0f;
                cc[nt][q] = v;
            }

        // softmax (rows r0 and r1, each spread over 4 lanes)
        float mx0 = -1e30f, mx1 = -1e30f;
#pragma unroll
        for (int nt = 0; nt < 8; ++nt) {
            mx0 = fmaxf(mx0, fmaxf(cc[nt][0], cc[nt][1]));
            mx1 = fmaxf(mx1, fmaxf(cc[nt][2], cc[nt][3]));
        }
        mx0 = fmaxf(mx0, __shfl_xor_sync(0xffffffffu, mx0, 1));
        mx0 = fmaxf(mx0, __shfl_xor_sync(0xffffffffu, mx0, 2));
        mx1 = fmaxf(mx1, __shfl_xor_sync(0xffffffffu, mx1, 1));
        mx1 = fmaxf(mx1, __shfl_xor_sync(0xffffffffu, mx1, 2));

        float s0 = 0.0f, s1 = 0.0f;
#pragma unroll
        for (int nt = 0; nt < 8; ++nt) {
            cc[nt][0] = __expf(cc[nt][0] - mx0);
            cc[nt][1] = __expf(cc[nt][1] - mx0);
            cc[nt][2] = __expf(cc[nt][2] - mx1);
            cc[nt][3] = __expf(cc[nt][3] - mx1);
            s0 += cc[nt][0] + cc[nt][1];
            s1 += cc[nt][2] + cc[nt][3];
        }
        s0 += __shfl_xor_sync(0xffffffffu, s0, 1);
        s0 += __shfl_xor_sync(0xffffffffu, s0, 2);
        s1 += __shfl_xor_sync(0xffffffffu, s1, 1);
        s1 += __shfl_xor_sync(0xffffffffu, s1, 2);
        const float inv0 = 1.0f / s0;
        const float inv1 = 1.0f / s1;

        // stage P (tf32 bits) for the PV A fragments
#pragma unroll
        for (int nt = 0; nt < 8; ++nt) {
            *(uint2*)(psw + g * 68 + nt * 8 + 2 * t) =
                make_uint2(f2tf(cc[nt][0]), f2tf(cc[nt][1]));
            *(uint2*)(psw + (g + 8) * 68 + nt * 8 + 2 * t) =
                make_uint2(f2tf(cc[nt][2]), f2tf(cc[nt][3]));
        }
        __syncwarp();

        // PV
        float out[4][4];
#pragma unroll
        for (int vt = 0; vt < 4; ++vt)
#pragma unroll
            for (int q = 0; q < 4; ++q) out[vt][q] = 0.0f;

#pragma unroll
        for (int kb = 0; kb < 8; ++kb) {
            unsigned a[4] = { psw[g * 68 + kb * 8 + t],
                              psw[(g + 8) * 68 + kb * 8 + t],
                              psw[g * 68 + kb * 8 + t + 4],
                              psw[(g + 8) * 68 + kb * 8 + t + 4] };
#pragma unroll
            for (int vt = 0; vt < 4; ++vt) {
                unsigned b[2] = { vv[(kb * 8 + t) * 32 + vt * 8 + g],
                                  vv[(kb * 8 + t + 4) * 32 + vt * 8 + g] };
                mma8(out[vt], a, b);
            }
        }

        // store to g_ao (tf32 bits)
        unsigned* d0 = g_ao + (((w << 6) | r0) << 8) + h * 32;
        unsigned* d1 = g_ao + (((w << 6) | r1) << 8) + h * 32;
#pragma unroll
        for (int vt = 0; vt < 4; ++vt) {
            *(uint2*)(d0 + vt * 8 + 2 * t) =
                make_uint2(f2tf(out[vt][0] * inv0), f2tf(out[vt][1] * inv0));
            *(uint2*)(d1 + vt * 8 + 2 * t) =
                make_uint2(f2tf(out[vt][2] * inv1), f2tf(out[vt][3] * inv1));
        }
        __syncwarp();
    }
}

// ============================================================
// Kernel 3: output projection + inverse window/roll scatter
// ============================================================
__global__ void __launch_bounds__(512)
swin_proj_kernel(const float* __restrict__ bo, float* __restrict__ out)
{
    extern __shared__ unsigned sm[];
    unsigned* Xs = sm;
    unsigned* Wt = sm + NSTG * XBUF;
    const unsigned smem_base = (unsigned)__cvta_generic_to_shared(sm);

    const int bw   = blockIdx.x;
    const int tid  = threadIdx.x;
    const int warp = tid >> 5;
    const int lane = tid & 31;
    const int g    = lane >> 2;
    const int t    = lane & 3;
    const int mw   = warp >> 2;
    const int nw   = warp & 3;

    const int arow  = tid >> 3;
    const int apart = tid & 7;
    const int bkk   = tid >> 6;
    const int bpart = tid & 63;
    const unsigned* W = g_wtf + 3 * 65536;
    const unsigned* Abase = g_ao + ((bw * 128) << 8);

#define LOAD_A(kc, st) do {                                                    \
        unsigned d0 = smem_base + (((st) * XBUF + arow * XCH + apart * 4) << 2); \
        cp16(d0, Abase + (arow << 8) + (kc) * 32 + apart * 4);                  \
        unsigned d1 = smem_base + (((st) * XBUF + (arow + 64) * XCH + apart * 4) << 2); \
        cp16(d1, Abase + ((arow + 64) << 8) + (kc) * 32 + apart * 4);           \
    } while (0)

#define LOAD_B(kc, st) do {                                                    \
        _Pragma("unroll")                                                      \
        for (int jj = 0; jj < 4; ++jj) {                                       \
            int kk = bkk + jj * 8;                                             \
            unsigned d = smem_base +                                           \
                ((NSTG * XBUF + (st) * WBUF + kk * WST + bpart * 4) << 2);     \
            cp16(d, W + (((kc) * 32 + kk) << 8) + bpart * 4);                  \
        }                                                                      \
    } while (0)

    float acc[2][8][4];
#pragma unroll
    for (int mt = 0; mt < 2; ++mt)
#pragma unroll
        for (int nt = 0; nt < 8; ++nt)
#pragma unroll
            for (int q = 0; q < 4; ++q) acc[mt][nt][q] = 0.0f;

    LOAD_A(0, 0); LOAD_B(0, 0); cp_commit();
    LOAD_A(1, 1); LOAD_B(1, 1); cp_commit();

#pragma unroll 1
    for (int kc = 0; kc < 8; ++kc) {
        if (kc + 2 < 8) {
            int st = (kc + 2) % 3;
            LOAD_A(kc + 2, st); LOAD_B(kc + 2, st);
        }
        cp_commit();
        cp_wait<2>();
        __syncthreads();

        const unsigned* XsS = Xs + (kc % 3) * XBUF;
        const unsigned* WtS = Wt + (kc % 3) * WBUF;
#pragma unroll
        for (int ks = 0; ks < 4; ++ks) {
            const int kb = ks * 8;
            unsigned a[2][4];
#pragma unroll
            for (int mt = 0; mt < 2; ++mt) {
                const unsigned* ar = XsS + (mw * 32 + mt * 16 + g) * XCH + kb + t;
                a[mt][0] = ar[0];
                a[mt][1] = ar[8 * XCH];
                a[mt][2] = ar[4];
                a[mt][3] = ar[8 * XCH + 4];
            }
            unsigned bf[8][2];
#pragma unroll
            for (int nt = 0; nt < 8; ++nt) {
                const unsigned* br = WtS + (kb + t) * WST + nw * 64 + nt * 8 + g;
                bf[nt][0] = br[0];
                bf[nt][1] = br[4 * WST];
            }
#pragma unroll
            for (int mt = 0; mt < 2; ++mt)
#pragma unroll
                for (int nt = 0; nt < 8; ++nt)
                    mma8(acc[mt][nt], a[mt], bf[nt]);
        }
        __syncthreads();
    }

    float2 bb[8];
#pragma unroll
    for (int nt = 0; nt < 8; ++nt)
        bb[nt] = *(const float2*)(bo + nw * 64 + nt * 8 + 2 * t);

#pragma unroll
    for (int mt = 0; mt < 2; ++mt)
#pragma unroll
        for (int rh = 0; rh < 2; ++rh)
#pragma unroll
            for (int nt = 0; nt < 8; ++nt) {
                int n   = mw * 32 + mt * 16 + rh * 8 + g;
                int wv  = bw * 2 + (n >> 6);
                int tok = n & 63;
                int b   = wv >> 6, wy = (wv >> 3) & 7, wx = wv & 7;
                int y   = ((wy << 3) + (tok >> 3) + 4) & 63;
                int xc  = ((wx << 3) + (tok & 7) + 4) & 63;
                int col = nw * 64 + nt * 8 + 2 * t;
                *(float2*)(out + (((b << 6) | y) << 14) + (xc << 8) + col) =
                    make_float2(acc[mt][nt][rh * 2] + bb[nt].x,
                                acc[mt][nt][rh * 2 + 1] + bb[nt].y);
            }
#undef LOAD_A
#undef LOAD_B
}

// ============================================================
extern "C" void kernel_launch(void* const* d_in, const int* in_sizes, int n_in,
                              void* d_out, int out_size)
{
    const float* x  = (const float*)d_in[0];
    const float* Wq = (const float*)d_in[1];
    const float* bq = (const float*)d_in[2];
    const float* Wk = (const float*)d_in[3];
    const float* bk = (const float*)d_in[4];
    const float* Wv = (const float*)d_in[5];
    const float* bv = (const float*)d_in[6];
    const float* Wo = (const float*)d_in[7];
    const float* bo = (const float*)d_in[8];
    const float* ls = (const float*)d_in[9];
    const float* w1 = (const float*)d_in[10];
    const float* b1 = (const float*)d_in[11];
    const float* w2 = (const float*)d_in[12];
    float* out = (float*)d_out;

    cudaFuncSetAttribute(swin_qkv_kernel,
                         cudaFuncAttributeMaxDynamicSharedMemorySize, G_SMEM);
    cudaFuncSetAttribute(swin_proj_kernel,
                         cudaFuncAttributeMaxDynamicSharedMemorySize, G_SMEM);

    swin_bias_kernel<<<225, 512>>>(ls, w1, b1, w2);
    swin_cvt_kernel<<<16640, 256>>>(x, Wq, Wk, Wv, Wo);
    swin_qkv_kernel<<<512, 512, G_SMEM>>>(bq, bk, bv);
    swin_attn_kernel<<<NWIN, 256>>>();
    swin_proj_kernel<<<512, 512, G_SMEM>>>(bo, out);
}

// round 6
// speedup vs baseline: 1.4827x; 1.4827x over previous
#include <cuda_runtime.h>

// SwinV2 shifted-window attention, B=16, H=W=64, C=256, heads=8, hd=32,
// window 8x8, shift 4x4  ->  1024 windows x 64 tokens.
//
// Round 6: MMA attention with proper operand supply: block=(window,head),
// 4 warps (one 16-row m-tile each), K/V staged coalesced into smem
// (K hi/lo split at staging), conflict-free fragment LDS, P staged
// per-warp. QK^T in 3xTF32, PV in tf32. q/k stored fp32 by QKV.

#define NWIN   1024
#define NTOK   64
#define CDIM   256
#define NHEAD  8
#define HD     32

// -------- scratch (device globals; no allocation) --------
__device__ float    g_q  [NWIN * NHEAD * NTOK * HD];  // normalized q fp32
__device__ float    g_k  [NWIN * NHEAD * NTOK * HD];  // normalized k fp32
__device__ unsigned g_v  [NWIN * NHEAD * NTOK * HD];  // v tf32 bits
__device__ unsigned g_ao [NWIN * NTOK * CDIM];        // attn out tf32 bits
__device__ unsigned g_xtf[16 * 64 * 64 * CDIM];       // x tf32 bits
__device__ unsigned g_wtf[4 * CDIM * CDIM];           // weights tf32 bits
__device__ float    g_bias16[NHEAD * 225];
__device__ float    g_scale[NHEAD];

// -------- helpers --------
__device__ __forceinline__ unsigned f2tf(float f) {
    unsigned u;
    asm("cvt.rna.tf32.f32 %0, %1;" : "=r"(u) : "f"(f));
    return u;
}
__device__ __forceinline__ void mma8(float* c, const unsigned* a, const unsigned* b) {
    asm volatile("mma.sync.aligned.m16n8k8.row.col.f32.tf32.tf32.f32 "
                 "{%0,%1,%2,%3},{%4,%5,%6,%7},{%8,%9},{%0,%1,%2,%3};"
                 : "+f"(c[0]), "+f"(c[1]), "+f"(c[2]), "+f"(c[3])
                 : "r"(a[0]), "r"(a[1]), "r"(a[2]), "r"(a[3]),
                   "r"(b[0]), "r"(b[1]));
}
__device__ __forceinline__ void cp16(unsigned dst, const void* src) {
    asm volatile("cp.async.cg.shared.global [%0], [%1], 16;" :: "r"(dst), "l"(src));
}
__device__ __forceinline__ void cp_commit() {
    asm volatile("cp.async.commit_group;");
}
template<int N> __device__ __forceinline__ void cp_wait() {
    asm volatile("cp.async.wait_group %0;" :: "n"(N));
}

// -------- GEMM smem geometry --------
#define XCH   36
#define WST   264
#define XBUF  (128 * XCH)
#define WBUF  (32 * WST)
#define NSTG  3
#define G_SMEM ((NSTG * (XBUF + WBUF) + 128) * 4)

// ============================================================
// Kernel 0: continuous-position-bias MLP
// ============================================================
__global__ void swin_bias_kernel(const float* __restrict__ ls,
                                 const float* __restrict__ w1,
                                 const float* __restrict__ b1,
                                 const float* __restrict__ w2)
{
    __shared__ float part[16][8];
    const int t   = blockIdx.x;
    const int i   = t / 15;
    const int j   = t % 15;
    const int tid = threadIdx.x;
    const int warp = tid >> 5;
    const int lane = tid & 31;

    float rh = (float)(i - 7) * (8.0f / 7.0f);
    float rw = (float)(j - 7) * (8.0f / 7.0f);
    rh = copysignf(log2f(fabsf(rh) + 1.0f) * (1.0f / 3.0f), rh);
    rw = copysignf(log2f(fabsf(rw) + 1.0f) * (1.0f / 3.0f), rw);

    float hv = fmaxf(0.0f, rh * w1[tid] + rw * w1[512 + tid] + b1[tid]);

    float p[8];
#pragma unroll
    for (int h = 0; h < 8; ++h) p[h] = hv * w2[tid * 8 + h];
#pragma unroll
    for (int off = 16; off; off >>= 1)
#pragma unroll
        for (int h = 0; h < 8; ++h) p[h] += __shfl_xor_sync(0xffffffffu, p[h], off);
    if (lane == 0)
#pragma unroll
        for (int h = 0; h < 8; ++h) part[warp][h] = p[h];
    __syncthreads();

    if (tid < 8) {
        float s = 0.0f;
#pragma unroll
        for (int g = 0; g < 16; ++g) s += part[g][tid];
        g_bias16[tid * 225 + t] = 16.0f / (1.0f + expf(-s));
    }
    if (blockIdx.x == 0 && tid < 8)
        g_scale[tid] = expf(fminf(ls[tid], 4.6051701860f));
}

// ============================================================
// Kernel 0b: convert x and weights to tf32 bits (once)
// ============================================================
__global__ void swin_cvt_kernel(const float* __restrict__ x,
                                const float* __restrict__ Wq,
                                const float* __restrict__ Wk,
                                const float* __restrict__ Wv,
                                const float* __restrict__ Wo)
{
    const int blk = blockIdx.x;
    const int tid = threadIdx.x;
    if (blk < 16384) {
        int i4 = blk * 256 + tid;
        float4 v = ((const float4*)x)[i4];
        ((uint4*)g_xtf)[i4] = make_uint4(f2tf(v.x), f2tf(v.y), f2tf(v.z), f2tf(v.w));
    } else {
        int r  = blk - 16384;
        int m  = r >> 6;
        int i4 = (r & 63) * 256 + tid;
        const float* W = (m == 0) ? Wq : (m == 1) ? Wk : (m == 2) ? Wv : Wo;
        float4 v = ((const float4*)W)[i4];
        ((uint4*)(g_wtf + m * 65536))[i4] =
            make_uint4(f2tf(v.x), f2tf(v.y), f2tf(v.z), f2tf(v.w));
    }
}

// ============================================================
// Kernel 1: QKV projection (tf32 MMA, cp.async 3-stage)
// ============================================================
__global__ void __launch_bounds__(512)
swin_qkv_kernel(const float* __restrict__ bq,
                const float* __restrict__ bk,
                const float* __restrict__ bv)
{
    extern __shared__ unsigned sm[];
    unsigned* Xs = sm;
    unsigned* Wt = sm + NSTG * XBUF;
    unsigned* rowbase = sm + NSTG * (XBUF + WBUF);
    const unsigned smem_base = (unsigned)__cvta_generic_to_shared(sm);

    const int bw   = blockIdx.x;
    const int tid  = threadIdx.x;
    const int warp = tid >> 5;
    const int lane = tid & 31;
    const int g    = lane >> 2;
    const int t    = lane & 3;
    const int mw   = warp >> 2;
    const int nw   = warp & 3;

    if (tid < 128) {
        int wv = bw * 2 + (tid >> 6);
        int b = wv >> 6, wy = (wv >> 3) & 7, wx = wv & 7;
        int tok = tid & 63;
        int sy = ((wy << 3) + (tok >> 3) + 4) & 63;
        int sx = ((wx << 3) + (tok & 7) + 4) & 63;
        rowbase[tid] = ((((b << 6) | sy) << 6) | sx) << 8;
    }
    __syncthreads();

    const int arow  = tid >> 3;
    const int apart = tid & 7;
    const unsigned rb0 = rowbase[arow];
    const unsigned rb1 = rowbase[arow + 64];
    const int bkk   = tid >> 6;
    const int bpart = tid & 63;

#define LOAD_A(kc, st) do {                                                    \
        unsigned d0 = smem_base + (((st) * XBUF + arow * XCH + apart * 4) << 2); \
        cp16(d0, g_xtf + rb0 + (kc) * 32 + apart * 4);                          \
        unsigned d1 = smem_base + (((st) * XBUF + (arow + 64) * XCH + apart * 4) << 2); \
        cp16(d1, g_xtf + rb1 + (kc) * 32 + apart * 4);                          \
    } while (0)

#define LOAD_B(W, kc, st) do {                                                 \
        _Pragma("unroll")                                                      \
        for (int jj = 0; jj < 4; ++jj) {                                       \
            int kk = bkk + jj * 8;                                             \
            unsigned d = smem_base +                                           \
                ((NSTG * XBUF + (st) * WBUF + kk * WST + bpart * 4) << 2);     \
            cp16(d, (W) + (((kc) * 32 + kk) << 8) + bpart * 4);                \
        }                                                                      \
    } while (0)

    const float* Bm[3] = {bq, bk, bv};

#pragma unroll 1
    for (int m = 0; m < 3; ++m) {
        const unsigned* W = g_wtf + m * 65536;
        float acc[2][8][4];
#pragma unroll
        for (int mt = 0; mt < 2; ++mt)
#pragma unroll
            for (int nt = 0; nt < 8; ++nt)
#pragma unroll
                for (int q = 0; q < 4; ++q) acc[mt][nt][q] = 0.0f;

        LOAD_A(0, 0); LOAD_B(W, 0, 0); cp_commit();
        LOAD_A(1, 1); LOAD_B(W, 1, 1); cp_commit();

#pragma unroll 1
        for (int kc = 0; kc < 8; ++kc) {
            if (kc + 2 < 8) {
                int st = (kc + 2) % 3;
                LOAD_A(kc + 2, st); LOAD_B(W, kc + 2, st);
            }
            cp_commit();
            cp_wait<2>();
            __syncthreads();

            const unsigned* XsS = Xs + (kc % 3) * XBUF;
            const unsigned* WtS = Wt + (kc % 3) * WBUF;
#pragma unroll
            for (int ks = 0; ks < 4; ++ks) {
                const int kb = ks * 8;
                unsigned a[2][4];
#pragma unroll
                for (int mt = 0; mt < 2; ++mt) {
                    const unsigned* ar = XsS + (mw * 32 + mt * 16 + g) * XCH + kb + t;
                    a[mt][0] = ar[0];
                    a[mt][1] = ar[8 * XCH];
                    a[mt][2] = ar[4];
                    a[mt][3] = ar[8 * XCH + 4];
                }
                unsigned bf[8][2];
#pragma unroll
                for (int nt = 0; nt < 8; ++nt) {
                    const unsigned* br = WtS + (kb + t) * WST + nw * 64 + nt * 8 + g;
                    bf[nt][0] = br[0];
                    bf[nt][1] = br[4 * WST];
                }
#pragma unroll
                for (int mt = 0; mt < 2; ++mt)
#pragma unroll
                    for (int nt = 0; nt < 8; ++nt)
                        mma8(acc[mt][nt], a[mt], bf[nt]);
            }
            __syncthreads();
        }

        float2 bb[8];
#pragma unroll
        for (int nt = 0; nt < 8; ++nt)
            bb[nt] = *(const float2*)(Bm[m] + nw * 64 + nt * 8 + 2 * t);
#pragma unroll
        for (int mt = 0; mt < 2; ++mt)
#pragma unroll
            for (int nt = 0; nt < 8; ++nt) {
                acc[mt][nt][0] += bb[nt].x;  acc[mt][nt][1] += bb[nt].y;
                acc[mt][nt][2] += bb[nt].x;  acc[mt][nt][3] += bb[nt].y;
            }

        if (m < 2) {
#pragma unroll
            for (int mt = 0; mt < 2; ++mt)
#pragma unroll
                for (int rh = 0; rh < 2; ++rh)
#pragma unroll
                    for (int hh = 0; hh < 2; ++hh) {
                        float s = 0.0f;
#pragma unroll
                        for (int k2 = 0; k2 < 4; ++k2) {
                            int nt = hh * 4 + k2;
                            s += acc[mt][nt][rh * 2]     * acc[mt][nt][rh * 2]
                               + acc[mt][nt][rh * 2 + 1] * acc[mt][nt][rh * 2 + 1];
                        }
                        s += __shfl_xor_sync(0xffffffffu, s, 1);
                        s += __shfl_xor_sync(0xffffffffu, s, 2);
                        float inv = 1.0f / fmaxf(sqrtf(s), 1e-12f);
#pragma unroll
                        for (int k2 = 0; k2 < 4; ++k2) {
                            int nt = hh * 4 + k2;
                            acc[mt][nt][rh * 2]     *= inv;
                            acc[mt][nt][rh * 2 + 1] *= inv;
                        }
                    }
        }

#pragma unroll
        for (int mt = 0; mt < 2; ++mt)
#pragma unroll
            for (int rh = 0; rh < 2; ++rh)
#pragma unroll
                for (int nt = 0; nt < 8; ++nt) {
                    int n    = mw * 32 + mt * 16 + rh * 8 + g;
                    int win  = bw * 2 + (n >> 6);
                    int tok  = n & 63;
                    int col  = nw * 64 + nt * 8 + 2 * t;
                    int head = col >> 5;
                    int d    = col & 31;
                    int off  = (((win << 3) | head) << 11) + (tok << 5) + d;
                    float vx = acc[mt][nt][rh * 2];
                    float vy = acc[mt][nt][rh * 2 + 1];
                    if (m == 0)      *(float2*)(g_q + off) = make_float2(vx, vy);
                    else if (m == 1) *(float2*)(g_k + off) = make_float2(vx, vy);
                    else             *(uint2*)(g_v + off)  = make_uint2(f2tf(vx), f2tf(vy));
                }
    }
#undef LOAD_A
#undef LOAD_B
}

// ============================================================
// Kernel 2: MMA attention. grid (1024, 8), 128 threads (4 warps).
// Warp wt owns rows [wt*16, wt*16+16). K/V staged in smem coalesced,
// K split hi/lo at staging. QK^T 3xTF32, PV tf32, P per-warp smem.
// ============================================================
__global__ void __launch_bounds__(128)
swin_attn_kernel()
{
    __shared__ unsigned khs[64 * 36];     // K hi tf32 (stride 36: conflict-free)
    __shared__ unsigned kls[64 * 36];     // K lo tf32
    __shared__ unsigned vss[64 * 40];     // V tf32 (stride 40: conflict-free)
    __shared__ unsigned ps[4][16 * 68];   // per-warp P tiles
    __shared__ float    bs[228];

    const int w    = blockIdx.x;
    const int h    = blockIdx.y;
    const int tid  = threadIdx.x;
    const int wt   = tid >> 5;
    const int lane = tid & 31;
    const int g    = lane >> 2;
    const int t    = lane & 3;
    const int base = ((w << 3) | h) << 11;

    // ---- stage K (hi/lo split) and V, coalesced ----
    const float4* kg = (const float4*)(g_k + base);
    const uint4*  vg = (const uint4*)(g_v + base);
#pragma unroll
    for (int it = 0; it < 4; ++it) {
        int i4  = tid + it * 128;         // 0..511
        int row = i4 >> 3;
        int c4  = (i4 & 7) << 2;
        float4 kv = kg[i4];
        unsigned hx = f2tf(kv.x), hy = f2tf(kv.y);
        unsigned hz = f2tf(kv.z), hw = f2tf(kv.w);
        *(uint4*)(khs + row * 36 + c4) = make_uint4(hx, hy, hz, hw);
        *(uint4*)(kls + row * 36 + c4) =
            make_uint4(f2tf(kv.x - __uint_as_float(hx)),
                       f2tf(kv.y - __uint_as_float(hy)),
                       f2tf(kv.z - __uint_as_float(hz)),
                       f2tf(kv.w - __uint_as_float(hw)));
        *(uint4*)(vss + row * 40 + c4) = vg[i4];
    }
    for (int i = tid; i < 225; i += 128) bs[i] = g_bias16[h * 225 + i];
    __syncthreads();

    const float sc = g_scale[h];
    const int wy = (w >> 3) & 7, wx = w & 7;
    const bool mhb = (wy == 7), mwb = (wx == 7);
    const int r0 = wt * 16 + g;
    const int r1 = r0 + 8;

    // ---- Q fragments from gmem, hi/lo split in regs ----
    const float* qf = g_q + base;
    unsigned aqh[4][4], aql[4][4];
#pragma unroll
    for (int ks = 0; ks < 4; ++ks) {
        int c0 = ks * 8 + t;
        float q0 = qf[r0 * 32 + c0];
        float q1 = qf[r1 * 32 + c0];
        float q2 = qf[r0 * 32 + c0 + 4];
        float q3 = qf[r1 * 32 + c0 + 4];
        aqh[ks][0] = f2tf(q0); aqh[ks][1] = f2tf(q1);
        aqh[ks][2] = f2tf(q2); aqh[ks][3] = f2tf(q3);
        aql[ks][0] = f2tf(q0 - __uint_as_float(aqh[ks][0]));
        aql[ks][1] = f2tf(q1 - __uint_as_float(aqh[ks][1]));
        aql[ks][2] = f2tf(q2 - __uint_as_float(aqh[ks][2]));
        aql[ks][3] = f2tf(q3 - __uint_as_float(aqh[ks][3]));
    }

    // ---- QK^T (3xTF32) ----
    float cc[8][4];
#pragma unroll
    for (int nt = 0; nt < 8; ++nt)
#pragma unroll
        for (int q = 0; q < 4; ++q) cc[nt][q] = 0.0f;

#pragma unroll
    for (int nt = 0; nt < 8; ++nt) {
#pragma unroll
        for (int ks = 0; ks < 4; ++ks) {
            int ca = (nt * 8 + g) * 36 + ks * 8 + t;
            unsigned bh[2] = { khs[ca], khs[ca + 4] };
            unsigned bl[2] = { kls[ca], kls[ca + 4] };
            mma8(cc[nt], aqh[ks], bh);
            mma8(cc[nt], aql[ks], bh);
            mma8(cc[nt], aqh[ks], bl);
        }
    }

    // ---- bias + mask ----
    const int ty0 = r0 >> 3, tx0 = r0 & 7;
    const int ty1 = r1 >> 3, tx1 = r1 & 7;
#pragma unroll
    for (int nt = 0; nt < 8; ++nt)
#pragma unroll
        for (int q = 0; q < 4; ++q) {
            int m  = nt * 8 + 2 * t + (q & 1);
            int my = m >> 3, mxc = m & 7;
            int ty = (q < 2) ? ty0 : ty1;
            int tx = (q < 2) ? tx0 : tx1;
            float v = cc[nt][q] * sc + bs[(ty - my + 7) * 15 + (tx - mxc + 7)];
            if (mhb && ((ty < 4) != (my < 4)))  v -= 100.0f;
            if (mwb && ((tx < 4) != (mxc < 4))) v -= 100.0f;
            cc[nt][q] = v;
        }

    // ---- softmax on fragments ----
    float mx0 = -1e30f, mx1 = -1e30f;
#pragma unroll
    for (int nt = 0; nt < 8; ++nt) {
        mx0 = fmaxf(mx0, fmaxf(cc[nt][0], cc[nt][1]));
        mx1 = fmaxf(mx1, fmaxf(cc[nt][2], cc[nt][3]));
    }
    mx0 = fmaxf(mx0, __shfl_xor_sync(0xffffffffu, mx0, 1));
    mx0 = fmaxf(mx0, __shfl_xor_sync(0xffffffffu, mx0, 2));
    mx1 = fmaxf(mx1, __shfl_xor_sync(0xffffffffu, mx1, 1));
    mx1 = fmaxf(mx1, __shfl_xor_sync(0xffffffffu, mx1, 2));

    float s0 = 0.0f, s1 = 0.0f;
#pragma unroll
    for (int nt = 0; nt < 8; ++nt) {
        cc[nt][0] = __expf(cc[nt][0] - mx0);
        cc[nt][1] = __expf(cc[nt][1] - mx0);
        cc[nt][2] = __expf(cc[nt][2] - mx1);
        cc[nt][3] = __expf(cc[nt][3] - mx1);
        s0 += cc[nt][0] + cc[nt][1];
        s1 += cc[nt][2] + cc[nt][3];
    }
    s0 += __shfl_xor_sync(0xffffffffu, s0, 1);
    s0 += __shfl_xor_sync(0xffffffffu, s0, 2);
    s1 += __shfl_xor_sync(0xffffffffu, s1, 1);
    s1 += __shfl_xor_sync(0xffffffffu, s1, 2);
    const float inv0 = 1.0f / s0;
    const float inv1 = 1.0f / s1;

    // ---- stage P (per-warp tile) ----
    unsigned* psw = ps[wt];
#pragma unroll
    for (int nt = 0; nt < 8; ++nt) {
        *(uint2*)(psw + g * 68 + nt * 8 + 2 * t) =
            make_uint2(f2tf(cc[nt][0]), f2tf(cc[nt][1]));
        *(uint2*)(psw + (g + 8) * 68 + nt * 8 + 2 * t) =
            make_uint2(f2tf(cc[nt][2]), f2tf(cc[nt][3]));
    }
    __syncwarp();

    // ---- PV ----
    float out[4][4];
#pragma unroll
    for (int vt = 0; vt < 4; ++vt)
#pragma unroll
        for (int q = 0; q < 4; ++q) out[vt][q] = 0.0f;

#pragma unroll
    for (int kb = 0; kb < 8; ++kb) {
        unsigned a[4] = { psw[g * 68 + kb * 8 + t],
                          psw[(g + 8) * 68 + kb * 8 + t],
                          psw[g * 68 + kb * 8 + t + 4],
                          psw[(g + 8) * 68 + kb * 8 + t + 4] };
#pragma unroll
        for (int vt = 0; vt < 4; ++vt) {
            unsigned b[2] = { vss[(kb * 8 + t) * 40 + vt * 8 + g],
                              vss[(kb * 8 + t + 4) * 40 + vt * 8 + g] };
            mma8(out[vt], a, b);
        }
    }

    // ---- store (tf32 bits) ----
    unsigned* d0 = g_ao + (((w << 6) | r0) << 8) + h * 32;
    unsigned* d1 = g_ao + (((w << 6) | r1) << 8) + h * 32;
#pragma unroll
    for (int vt = 0; vt < 4; ++vt) {
        *(uint2*)(d0 + vt * 8 + 2 * t) =
            make_uint2(f2tf(out[vt][0] * inv0), f2tf(out[vt][1] * inv0));
        *(uint2*)(d1 + vt * 8 + 2 * t) =
            make_uint2(f2tf(out[vt][2] * inv1), f2tf(out[vt][3] * inv1));
    }
}

// ============================================================
// Kernel 3: output projection + inverse window/roll scatter
// ============================================================
__global__ void __launch_bounds__(512)
swin_proj_kernel(const float* __restrict__ bo, float* __restrict__ out)
{
    extern __shared__ unsigned sm[];
    unsigned* Xs = sm;
    unsigned* Wt = sm + NSTG * XBUF;
    const unsigned smem_base = (unsigned)__cvta_generic_to_shared(sm);

    const int bw   = blockIdx.x;
    const int tid  = threadIdx.x;
    const int warp = tid >> 5;
    const int lane = tid & 31;
    const int g    = lane >> 2;
    const int t    = lane & 3;
    const int mw   = warp >> 2;
    const int nw   = warp & 3;

    const int arow  = tid >> 3;
    const int apart = tid & 7;
    const int bkk   = tid >> 6;
    const int bpart = tid & 63;
    const unsigned* W = g_wtf + 3 * 65536;
    const unsigned* Abase = g_ao + ((bw * 128) << 8);

#define LOAD_A(kc, st) do {                                                    \
        unsigned d0 = smem_base + (((st) * XBUF + arow * XCH + apart * 4) << 2); \
        cp16(d0, Abase + (arow << 8) + (kc) * 32 + apart * 4);                  \
        unsigned d1 = smem_base + (((st) * XBUF + (arow + 64) * XCH + apart * 4) << 2); \
        cp16(d1, Abase + ((arow + 64) << 8) + (kc) * 32 + apart * 4);           \
    } while (0)

#define LOAD_B(kc, st) do {                                                    \
        _Pragma("unroll")                                                      \
        for (int jj = 0; jj < 4; ++jj) {                                       \
            int kk = bkk + jj * 8;                                             \
            unsigned d = smem_base +                                           \
                ((NSTG * XBUF + (st) * WBUF + kk * WST + bpart * 4) << 2);     \
            cp16(d, W + (((kc) * 32 + kk) << 8) + bpart * 4);                  \
        }                                                                      \
    } while (0)

    float acc[2][8][4];
#pragma unroll
    for (int mt = 0; mt < 2; ++mt)
#pragma unroll
        for (int nt = 0; nt < 8; ++nt)
#pragma unroll
            for (int q = 0; q < 4; ++q) acc[mt][nt][q] = 0.0f;

    LOAD_A(0, 0); LOAD_B(0, 0); cp_commit();
    LOAD_A(1, 1); LOAD_B(1, 1); cp_commit();

#pragma unroll 1
    for (int kc = 0; kc < 8; ++kc) {
        if (kc + 2 < 8) {
            int st = (kc + 2) % 3;
            LOAD_A(kc + 2, st); LOAD_B(kc + 2, st);
        }
        cp_commit();
        cp_wait<2>();
        __syncthreads();

        const unsigned* XsS = Xs + (kc % 3) * XBUF;
        const unsigned* WtS = Wt + (kc % 3) * WBUF;
#pragma unroll
        for (int ks = 0; ks < 4; ++ks) {
            const int kb = ks * 8;
            unsigned a[2][4];
#pragma unroll
            for (int mt = 0; mt < 2; ++mt) {
                const unsigned* ar = XsS + (mw * 32 + mt * 16 + g) * XCH + kb + t;
                a[mt][0] = ar[0];
                a[mt][1] = ar[8 * XCH];
                a[mt][2] = ar[4];
                a[mt][3] = ar[8 * XCH + 4];
            }
            unsigned bf[8][2];
#pragma unroll
            for (int nt = 0; nt < 8; ++nt) {
                const unsigned* br = WtS + (kb + t) * WST + nw * 64 + nt * 8 + g;
                bf[nt][0] = br[0];
                bf[nt][1] = br[4 * WST];
            }
#pragma unroll
            for (int mt = 0; mt < 2; ++mt)
#pragma unroll
                for (int nt = 0; nt < 8; ++nt)
                    mma8(acc[mt][nt], a[mt], bf[nt]);
        }
        __syncthreads();
    }

    float2 bb[8];
#pragma unroll
    for (int nt = 0; nt < 8; ++nt)
        bb[nt] = *(const float2*)(bo + nw * 64 + nt * 8 + 2 * t);

#pragma unroll
    for (int mt = 0; mt < 2; ++mt)
#pragma unroll
        for (int rh = 0; rh < 2; ++rh)
#pragma unroll
            for (int nt = 0; nt < 8; ++nt) {
                int n   = mw * 32 + mt * 16 + rh * 8 + g;
                int wv  = bw * 2 + (n >> 6);
                int tok = n & 63;
                int b   = wv >> 6, wy = (wv >> 3) & 7, wx = wv & 7;
                int y   = ((wy << 3) + (tok >> 3) + 4) & 63;
                int xc  = ((wx << 3) + (tok & 7) + 4) & 63;
                int col = nw * 64 + nt * 8 + 2 * t;
                *(float2*)(out + (((b << 6) | y) << 14) + (xc << 8) + col) =
                    make_float2(acc[mt][nt][rh * 2] + bb[nt].x,
                                acc[mt][nt][rh * 2 + 1] + bb[nt].y);
            }
#undef LOAD_A
#undef LOAD_B
}

// ============================================================
extern "C" void kernel_launch(void* const* d_in, const int* in_sizes, int n_in,
                              void* d_out, int out_size)
{
    const float* x  = (const float*)d_in[0];
    const float* Wq = (const float*)d_in[1];
    const float* bq = (const float*)d_in[2];
    const float* Wk = (const float*)d_in[3];
    const float* bk = (const float*)d_in[4];
    const float* Wv = (const float*)d_in[5];
    const float* bv = (const float*)d_in[6];
    const float* Wo = (const float*)d_in[7];
    const float* bo = (const float*)d_in[8];
    const float* ls = (const float*)d_in[9];
    const float* w1 = (const float*)d_in[10];
    const float* b1 = (const float*)d_in[11];
    const float* w2 = (const float*)d_in[12];
    float* out = (float*)d_out;

    cudaFuncSetAttribute(swin_qkv_kernel,
                         cudaFuncAttributeMaxDynamicSharedMemorySize, G_SMEM);
    cudaFuncSetAttribute(swin_proj_kernel,
                         cudaFuncAttributeMaxDynamicSharedMemorySize, G_SMEM);

    swin_bias_kernel<<<225, 512>>>(ls, w1, b1, w2);
    swin_cvt_kernel<<<16640, 256>>>(x, Wq, Wk, Wv, Wo);
    swin_qkv_kernel<<<512, 512, G_SMEM>>>(bq, bk, bv);
    swin_attn_kernel<<<dim3(NWIN, NHEAD), 128>>>();
    swin_proj_kernel<<<512, 512, G_SMEM>>>(bo, out);
}

// round 8
// speedup vs baseline: 1.9515x; 1.3162x over previous
#include <cuda_runtime.h>
#include <cuda_fp16.h>

// SwinV2 shifted-window attention, B=16, H=W=64, C=256, heads=8, hd=32.
// Round 8: projection GEMMs on legacy mma.sync m16n8k16 fp16 (fp32 accum)
// -- half the MMA instructions and half the operand traffic of tf32 --
// with a 3-stage cp.async pipeline. Attention = round 6 (3xTF32 QK + tf32
// PV), output packed fp16. (tcgen05 unavailable: PTX target is sm_103.)

#define NWIN   1024
#define NTOK   64
#define CDIM   256
#define NHEAD  8
#define HD     32

// -------- scratch (device globals; no allocation) --------
__device__ float          g_q  [NWIN * NHEAD * NTOK * HD];   // normalized q fp32
__device__ float          g_k  [NWIN * NHEAD * NTOK * HD];   // normalized k fp32
__device__ unsigned       g_v  [NWIN * NHEAD * NTOK * HD];   // v tf32 bits
__device__ unsigned short g_ao [NWIN * NTOK * CDIM];         // attn out fp16
__device__ unsigned short g_xh [16 * 64 * 64 * CDIM];        // x fp16
__device__ unsigned short g_wh [4 * CDIM * CDIM];            // W^T fp16 [n][k]
__device__ float          g_bias16[NHEAD * 225];
__device__ float          g_scale[NHEAD];

// -------- helpers --------
__device__ __forceinline__ unsigned f2tf(float f) {
    unsigned u;
    asm("cvt.rna.tf32.f32 %0, %1;" : "=r"(u) : "f"(f));
    return u;
}
// pack two floats into f16x2: lo half = first arg
__device__ __forceinline__ unsigned pkh(float lo, float hi) {
    unsigned r;
    asm("cvt.rn.f16x2.f32 %0, %1, %2;" : "=r"(r) : "f"(hi), "f"(lo));
    return r;
}
// tf32 m16n8k8 (attention)
__device__ __forceinline__ void mma8(float* c, const unsigned* a, const unsigned* b) {
    asm volatile("mma.sync.aligned.m16n8k8.row.col.f32.tf32.tf32.f32 "
                 "{%0,%1,%2,%3},{%4,%5,%6,%7},{%8,%9},{%0,%1,%2,%3};"
                 : "+f"(c[0]), "+f"(c[1]), "+f"(c[2]), "+f"(c[3])
                 : "r"(a[0]), "r"(a[1]), "r"(a[2]), "r"(a[3]),
                   "r"(b[0]), "r"(b[1]));
}
// fp16 m16n8k16 (projections)
__device__ __forceinline__ void mma16(float* c, const unsigned* a, const unsigned* b) {
    asm volatile("mma.sync.aligned.m16n8k16.row.col.f32.f16.f16.f32 "
                 "{%0,%1,%2,%3},{%4,%5,%6,%7},{%8,%9},{%0,%1,%2,%3};"
                 : "+f"(c[0]), "+f"(c[1]), "+f"(c[2]), "+f"(c[3])
                 : "r"(a[0]), "r"(a[1]), "r"(a[2]), "r"(a[3]),
                   "r"(b[0]), "r"(b[1]));
}
__device__ __forceinline__ void cp16(unsigned dst, const void* src) {
    asm volatile("cp.async.cg.shared.global [%0], [%1], 16;" :: "r"(dst), "l"(src));
}
__device__ __forceinline__ void cp_commit() {
    asm volatile("cp.async.commit_group;");
}
template<int N> __device__ __forceinline__ void cp_wait() {
    asm volatile("cp.async.wait_group %0;" :: "n"(N));
}

// -------- fp16 GEMM smem geometry --------
// A: 128 rows x 64 f16 chunk, row stride 72 f16 (144 B)  -> u32 stride 36
// B: 256 rows x 64 f16 chunk, row stride 72 f16
// u32-stride 36 mod 32 == 4  => fragment LDS word index = 4g+t, conflict-free
#define A_BYTES   (128 * 144)             // 18432
#define STG_BYTES (A_BYTES + 256 * 144)   // 55296
#define SM_ROWB   64
#define SM_BIAS   1024
#define SM_BUF    4096
#define G_SMEM    (SM_BUF + 3 * STG_BYTES)   // 169984 B

// ============================================================
// Kernel 0: continuous-position-bias MLP
// ============================================================
__global__ void swin_bias_kernel(const float* __restrict__ ls,
                                 const float* __restrict__ w1,
                                 const float* __restrict__ b1,
                                 const float* __restrict__ w2)
{
    __shared__ float part[16][8];
    const int t   = blockIdx.x;
    const int i   = t / 15;
    const int j   = t % 15;
    const int tid = threadIdx.x;
    const int warp = tid >> 5;
    const int lane = tid & 31;

    float rh = (float)(i - 7) * (8.0f / 7.0f);
    float rw = (float)(j - 7) * (8.0f / 7.0f);
    rh = copysignf(log2f(fabsf(rh) + 1.0f) * (1.0f / 3.0f), rh);
    rw = copysignf(log2f(fabsf(rw) + 1.0f) * (1.0f / 3.0f), rw);

    float hv = fmaxf(0.0f, rh * w1[tid] + rw * w1[512 + tid] + b1[tid]);

    float p[8];
#pragma unroll
    for (int h = 0; h < 8; ++h) p[h] = hv * w2[tid * 8 + h];
#pragma unroll
    for (int off = 16; off; off >>= 1)
#pragma unroll
        for (int h = 0; h < 8; ++h) p[h] += __shfl_xor_sync(0xffffffffu, p[h], off);
    if (lane == 0)
#pragma unroll
        for (int h = 0; h < 8; ++h) part[warp][h] = p[h];
    __syncthreads();

    if (tid < 8) {
        float s = 0.0f;
#pragma unroll
        for (int g = 0; g < 16; ++g) s += part[g][tid];
        g_bias16[tid * 225 + t] = 16.0f / (1.0f + expf(-s));
    }
    if (blockIdx.x == 0 && tid < 8)
        g_scale[tid] = expf(fminf(ls[tid], 4.6051701860f));
}

// ============================================================
// Kernel 0b: x -> fp16; W -> transposed fp16 [n][k]
// ============================================================
__global__ void swin_cvt_kernel(const float* __restrict__ x,
                                const float* __restrict__ Wq,
                                const float* __restrict__ Wk,
                                const float* __restrict__ Wv,
                                const float* __restrict__ Wo)
{
    const int blk = blockIdx.x;
    const int tid = threadIdx.x;
    if (blk < 16384) {
        int i4 = blk * 256 + tid;
        float4 v = ((const float4*)x)[i4];
        ((uint2*)g_xh)[i4] = make_uint2(pkh(v.x, v.y), pkh(v.z, v.w));
    } else {
        int r = blk - 16384;              // 0..255 (64 blocks per matrix)
        int m = r >> 6;
        const float* W = (m == 0) ? Wq : (m == 1) ? Wk : (m == 2) ? Wv : Wo;
        int idx = (r & 63) * 256 + tid;   // 0..16383
        int n  = idx >> 6;
        int k4 = (idx & 63) * 4;
        float a0 = W[(k4 + 0) * 256 + n];
        float a1 = W[(k4 + 1) * 256 + n];
        float a2 = W[(k4 + 2) * 256 + n];
        float a3 = W[(k4 + 3) * 256 + n];
        ((uint2*)(g_wh + m * 65536))[idx >> 0] =
            make_uint2(pkh(a0, a1), pkh(a2, a3));
    }
}

// ============================================================
// Kernel 1: QKV projection, fp16 m16n8k16, 3-stage cp.async.
// grid 512 (2 windows = M128), 512 threads (16 warps: 4M x 4N).
// 12 tiles: (matrix m = ts>>2, K-chunk c = ts&3), K-chunk = 64 f16.
// ============================================================
__global__ void __launch_bounds__(512)
swin_qkv_kernel(const float* __restrict__ bq,
                const float* __restrict__ bk,
                const float* __restrict__ bv)
{
    extern __shared__ char smem[];
    const unsigned sb = (unsigned)__cvta_generic_to_shared(smem);
    unsigned* rowb_s = (unsigned*)(smem + SM_ROWB);
    float*    bias_s = (float*)(smem + SM_BIAS);

    const int bw   = blockIdx.x;
    const int tid  = threadIdx.x;
    const int warp = tid >> 5;
    const int lane = tid & 31;
    const int g    = lane >> 2;
    const int t    = lane & 3;
    const int mw   = warp >> 2;           // M 32-slice
    const int nq   = warp & 3;            // N 64-slice

    if (tid < 128) {
        int wv = bw * 2 + (tid >> 6);
        int b = wv >> 6, wy = (wv >> 3) & 7, wx = wv & 7;
        int tok = tid & 63;
        int sy = ((wy << 3) + (tok >> 3) + 4) & 63;
        int sx = ((wx << 3) + (tok & 7) + 4) & 63;
        rowb_s[tid] = ((((b << 6) | sy) << 6) | sx) << 8;
    }
    if (tid < 256) {
        bias_s[tid]       = bq[tid];
        bias_s[256 + tid] = bk[tid];
        bias_s[512 + tid] = bv[tid];
    }
    __syncthreads();

    const int srow = tid >> 3;            // 0..63
    const int sjj  = tid & 7;
    const unsigned rb0 = rowb_s[srow];
    const unsigned rb1 = rowb_s[srow + 64];
    const unsigned asto0 = srow * 144 + sjj * 16;
    const unsigned asto1 = (srow + 64) * 144 + sjj * 16;

#define STAGE(wm_, c_, st_) do {                                               \
        unsigned _a = sb + SM_BUF + (st_) * STG_BYTES;                         \
        cp16(_a + asto0, g_xh + rb0 + (c_) * 64 + sjj * 8);                    \
        cp16(_a + asto1, g_xh + rb1 + (c_) * 64 + sjj * 8);                    \
        unsigned _bB = _a + A_BYTES;                                           \
        _Pragma("unroll")                                                      \
        for (int _i = 0; _i < 4; ++_i) {                                       \
            int _n = srow + _i * 64;                                           \
            cp16(_bB + _n * 144 + sjj * 16,                                    \
                 (wm_) + _n * 256 + (c_) * 64 + sjj * 8);                      \
        }                                                                      \
        cp_commit();                                                           \
    } while (0)

    STAGE(g_wh, 0, 0);
    STAGE(g_wh, 1, 1);

    float acc[2][8][4];

#pragma unroll 1
    for (int ts = 0; ts < 12; ++ts) {
        const int m  = ts >> 2;
        const int c  = ts & 3;
        const int st = ts % 3;

        if (c == 0) {
#pragma unroll
            for (int mt = 0; mt < 2; ++mt)
#pragma unroll
                for (int nt = 0; nt < 8; ++nt)
#pragma unroll
                    for (int q = 0; q < 4; ++q) acc[mt][nt][q] = 0.0f;
        }

        if (ts == 11) cp_wait<0>(); else cp_wait<1>();
        __syncthreads();

        if (ts + 2 < 12) {
            int t2 = ts + 2;
            const unsigned short* wm = g_wh + (t2 >> 2) * 65536;
            STAGE(wm, t2 & 3, t2 % 3);
        }

        const unsigned* Xs = (const unsigned*)(smem + SM_BUF + st * STG_BYTES);
        const unsigned* Bs = Xs + (A_BYTES >> 2);
#pragma unroll
        for (int ks = 0; ks < 4; ++ks) {     // 4 x k16 steps
            unsigned a[2][4];
#pragma unroll
            for (int mt = 0; mt < 2; ++mt) {
                const unsigned* ar = Xs + (mw * 32 + mt * 16 + g) * 36 + ks * 8 + t;
                a[mt][0] = ar[0];
                a[mt][1] = ar[8 * 36];
                a[mt][2] = ar[4];
                a[mt][3] = ar[8 * 36 + 4];
            }
            unsigned bf[8][2];
#pragma unroll
            for (int nt = 0; nt < 8; ++nt) {
                const unsigned* br = Bs + (nq * 64 + nt * 8 + g) * 36 + ks * 8 + t;
                bf[nt][0] = br[0];
                bf[nt][1] = br[4];
            }
#pragma unroll
            for (int mt = 0; mt < 2; ++mt)
#pragma unroll
                for (int nt = 0; nt < 8; ++nt)
                    mma16(acc[mt][nt], a[mt], bf[nt]);
        }

        if (c == 3) {
            // epilogue for matrix m
            float2 bb[8];
#pragma unroll
            for (int nt = 0; nt < 8; ++nt)
                bb[nt] = *(float2*)(bias_s + m * 256 + nq * 64 + nt * 8 + 2 * t);
#pragma unroll
            for (int mt = 0; mt < 2; ++mt)
#pragma unroll
                for (int nt = 0; nt < 8; ++nt) {
                    acc[mt][nt][0] += bb[nt].x;  acc[mt][nt][1] += bb[nt].y;
                    acc[mt][nt][2] += bb[nt].x;  acc[mt][nt][3] += bb[nt].y;
                }

            if (m < 2) {
#pragma unroll
                for (int mt = 0; mt < 2; ++mt)
#pragma unroll
                    for (int rh = 0; rh < 2; ++rh)
#pragma unroll
                        for (int hh = 0; hh < 2; ++hh) {
                            float s = 0.0f;
#pragma unroll
                            for (int k2 = 0; k2 < 4; ++k2) {
                                int nt = hh * 4 + k2;
                                s += acc[mt][nt][rh * 2]     * acc[mt][nt][rh * 2]
                                   + acc[mt][nt][rh * 2 + 1] * acc[mt][nt][rh * 2 + 1];
                            }
                            s += __shfl_xor_sync(0xffffffffu, s, 1);
                            s += __shfl_xor_sync(0xffffffffu, s, 2);
                            float inv = 1.0f / fmaxf(sqrtf(s), 1e-12f);
#pragma unroll
                            for (int k2 = 0; k2 < 4; ++k2) {
                                int nt = hh * 4 + k2;
                                acc[mt][nt][rh * 2]     *= inv;
                                acc[mt][nt][rh * 2 + 1] *= inv;
                            }
                        }
            }

#pragma unroll
            for (int mt = 0; mt < 2; ++mt)
#pragma unroll
                for (int rh = 0; rh < 2; ++rh)
#pragma unroll
                    for (int nt = 0; nt < 8; ++nt) {
                        int n    = mw * 32 + mt * 16 + rh * 8 + g;
                        int win  = bw * 2 + (n >> 6);
                        int tok  = n & 63;
                        int col  = nq * 64 + nt * 8 + 2 * t;
                        int head = col >> 5;
                        int d    = col & 31;
                        int off  = (((win << 3) | head) << 11) + (tok << 5) + d;
                        float vx = acc[mt][nt][rh * 2];
                        float vy = acc[mt][nt][rh * 2 + 1];
                        if (m == 0)      *(float2*)(g_q + off) = make_float2(vx, vy);
                        else if (m == 1) *(float2*)(g_k + off) = make_float2(vx, vy);
                        else             *(uint2*)(g_v + off)  = make_uint2(f2tf(vx), f2tf(vy));
                    }
        }
        __syncthreads();
    }
#undef STAGE
}

// ============================================================
// Kernel 2: MMA attention (round 6), output packed fp16.
// grid (1024, 8), 128 threads (4 warps, one 16-row m-tile each).
// ============================================================
__global__ void __launch_bounds__(128)
swin_attn_kernel()
{
    __shared__ unsigned khs[64 * 36];
    __shared__ unsigned kls[64 * 36];
    __shared__ unsigned vss[64 * 40];
    __shared__ unsigned ps[4][16 * 68];
    __shared__ float    bs[228];

    const int w    = blockIdx.x;
    const int h    = blockIdx.y;
    const int tid  = threadIdx.x;
    const int wt   = tid >> 5;
    const int lane = tid & 31;
    const int g    = lane >> 2;
    const int t    = lane & 3;
    const int base = ((w << 3) | h) << 11;

    const float4* kg = (const float4*)(g_k + base);
    const uint4*  vg = (const uint4*)(g_v + base);
#pragma unroll
    for (int it = 0; it < 4; ++it) {
        int i4  = tid + it * 128;
        int row = i4 >> 3;
        int c4  = (i4 & 7) << 2;
        float4 kv = kg[i4];
        unsigned hx = f2tf(kv.x), hy = f2tf(kv.y);
        unsigned hz = f2tf(kv.z), hw = f2tf(kv.w);
        *(uint4*)(khs + row * 36 + c4) = make_uint4(hx, hy, hz, hw);
        *(uint4*)(kls + row * 36 + c4) =
            make_uint4(f2tf(kv.x - __uint_as_float(hx)),
                       f2tf(kv.y - __uint_as_float(hy)),
                       f2tf(kv.z - __uint_as_float(hz)),
                       f2tf(kv.w - __uint_as_float(hw)));
        *(uint4*)(vss + row * 40 + c4) = vg[i4];
    }
    for (int i = tid; i < 225; i += 128) bs[i] = g_bias16[h * 225 + i];
    __syncthreads();

    const float sc = g_scale[h];
    const int wy = (w >> 3) & 7, wx = w & 7;
    const bool mhb = (wy == 7), mwb = (wx == 7);
    const int r0 = wt * 16 + g;
    const int r1 = r0 + 8;

    const float* qf = g_q + base;
    unsigned aqh[4][4], aql[4][4];
#pragma unroll
    for (int ks = 0; ks < 4; ++ks) {
        int c0 = ks * 8 + t;
        float q0 = qf[r0 * 32 + c0];
        float q1 = qf[r1 * 32 + c0];
        float q2 = qf[r0 * 32 + c0 + 4];
        float q3 = qf[r1 * 32 + c0 + 4];
        aqh[ks][0] = f2tf(q0); aqh[ks][1] = f2tf(q1);
        aqh[ks][2] = f2tf(q2); aqh[ks][3] = f2tf(q3);
        aql[ks][0] = f2tf(q0 - __uint_as_float(aqh[ks][0]));
        aql[ks][1] = f2tf(q1 - __uint_as_float(aqh[ks][1]));
        aql[ks][2] = f2tf(q2 - __uint_as_float(aqh[ks][2]));
        aql[ks][3] = f2tf(q3 - __uint_as_float(aqh[ks][3]));
    }

    float cc[8][4];
#pragma unroll
    for (int nt = 0; nt < 8; ++nt)
#pragma unroll
        for (int q = 0; q < 4; ++q) cc[nt][q] = 0.0f;

#pragma unroll
    for (int nt = 0; nt < 8; ++nt) {
#pragma unroll
        for (int ks = 0; ks < 4; ++ks) {
            int ca = (nt * 8 + g) * 36 + ks * 8 + t;
            unsigned bh[2] = { khs[ca], khs[ca + 4] };
            unsigned bl[2] = { kls[ca], kls[ca + 4] };
            mma8(cc[nt], aqh[ks], bh);
            mma8(cc[nt], aql[ks], bh);
            mma8(cc[nt], aqh[ks], bl);
        }
    }

    const int ty0 = r0 >> 3, tx0 = r0 & 7;
    const int ty1 = r1 >> 3, tx1 = r1 & 7;
#pragma unroll
    for (int nt = 0; nt < 8; ++nt)
#pragma unroll
        for (int q = 0; q < 4; ++q) {
            int m  = nt * 8 + 2 * t + (q & 1);
            int my = m >> 3, mxc = m & 7;
            int ty = (q < 2) ? ty0 : ty1;
            int tx = (q < 2) ? tx0 : tx1;
            float v = cc[nt][q] * sc + bs[(ty - my + 7) * 15 + (tx - mxc + 7)];
            if (mhb && ((ty < 4) != (my < 4)))  v -= 100.0f;
            if (mwb && ((tx < 4) != (mxc < 4))) v -= 100.0f;
            cc[nt][q] = v;
        }

    float mx0 = -1e30f, mx1 = -1e30f;
#pragma unroll
    for (int nt = 0; nt < 8; ++nt) {
        mx0 = fmaxf(mx0, fmaxf(cc[nt][0], cc[nt][1]));
        mx1 = fmaxf(mx1, fmaxf(cc[nt][2], cc[nt][3]));
    }
    mx0 = fmaxf(mx0, __shfl_xor_sync(0xffffffffu, mx0, 1));
    mx0 = fmaxf(mx0, __shfl_xor_sync(0xffffffffu, mx0, 2));
    mx1 = fmaxf(mx1, __shfl_xor_sync(0xffffffffu, mx1, 1));
    mx1 = fmaxf(mx1, __shfl_xor_sync(0xffffffffu, mx1, 2));

    float s0 = 0.0f, s1 = 0.0f;
#pragma unroll
    for (int nt = 0; nt < 8; ++nt) {
        cc[nt][0] = __expf(cc[nt][0] - mx0);
        cc[nt][1] = __expf(cc[nt][1] - mx0);
        cc[nt][2] = __expf(cc[nt][2] - mx1);
        cc[nt][3] = __expf(cc[nt][3] - mx1);
        s0 += cc[nt][0] + cc[nt][1];
        s1 += cc[nt][2] + cc[nt][3];
    }
    s0 += __shfl_xor_sync(0xffffffffu, s0, 1);
    s0 += __shfl_xor_sync(0xffffffffu, s0, 2);
    s1 += __shfl_xor_sync(0xffffffffu, s1, 1);
    s1 += __shfl_xor_sync(0xffffffffu, s1, 2);
    const float inv0 = 1.0f / s0;
    const float inv1 = 1.0f / s1;

    unsigned* psw = ps[wt];
#pragma unroll
    for (int nt = 0; nt < 8; ++nt) {
        *(uint2*)(psw + g * 68 + nt * 8 + 2 * t) =
            make_uint2(f2tf(cc[nt][0]), f2tf(cc[nt][1]));
        *(uint2*)(psw + (g + 8) * 68 + nt * 8 + 2 * t) =
            make_uint2(f2tf(cc[nt][2]), f2tf(cc[nt][3]));
    }
    __syncwarp();

    float out[4][4];
#pragma unroll
    for (int vt = 0; vt < 4; ++vt)
#pragma unroll
        for (int q = 0; q < 4; ++q) out[vt][q] = 0.0f;

#pragma unroll
    for (int kb = 0; kb < 8; ++kb) {
        unsigned a[4] = { psw[g * 68 + kb * 8 + t],
                          psw[(g + 8) * 68 + kb * 8 + t],
                          psw[g * 68 + kb * 8 + t + 4],
                          psw[(g + 8) * 68 + kb * 8 + t + 4] };
#pragma unroll
        for (int vt = 0; vt < 4; ++vt) {
            unsigned b[2] = { vss[(kb * 8 + t) * 40 + vt * 8 + g],
                              vss[(kb * 8 + t + 4) * 40 + vt * 8 + g] };
            mma8(out[vt], a, b);
        }
    }

    // store fp16 (paired f16x2 words)
    const int d0i = (((w << 6) | r0) << 8) + h * 32;
    const int d1i = (((w << 6) | r1) << 8) + h * 32;
    unsigned* ao32 = (unsigned*)g_ao;
#pragma unroll
    for (int vt = 0; vt < 4; ++vt) {
        ao32[(d0i + vt * 8 + 2 * t) >> 1] = pkh(out[vt][0] * inv0, out[vt][1] * inv0);
        ao32[(d1i + vt * 8 + 2 * t) >> 1] = pkh(out[vt][2] * inv1, out[vt][3] * inv1);
    }
}

// ============================================================
// Kernel 3: output projection fp16 m16n8k16 + inverse window/roll scatter.
// grid 512, 512 threads, 4 K-chunks, 3-stage pipeline.
// ============================================================
__global__ void __launch_bounds__(512)
swin_proj_kernel(const float* __restrict__ bo, float* __restrict__ out)
{
    extern __shared__ char smem[];
    const unsigned sb = (unsigned)__cvta_generic_to_shared(smem);
    float* bias_s = (float*)(smem + SM_BIAS);

    const int bw   = blockIdx.x;
    const int tid  = threadIdx.x;
    const int warp = tid >> 5;
    const int lane = tid & 31;
    const int g    = lane >> 2;
    const int t    = lane & 3;
    const int mw   = warp >> 2;
    const int nq   = warp & 3;

    if (tid < 256) bias_s[tid] = bo[tid];
    __syncthreads();

    const int srow = tid >> 3;
    const int sjj  = tid & 7;
    const unsigned asto0 = srow * 144 + sjj * 16;
    const unsigned asto1 = (srow + 64) * 144 + sjj * 16;
    const unsigned short* wh = g_wh + 3 * 65536;
    const int abase = bw * 128 * 256;

#define STAGE(c_, st_) do {                                                    \
        unsigned _a = sb + SM_BUF + (st_) * STG_BYTES;                         \
        cp16(_a + asto0, g_ao + abase + srow * 256 + (c_) * 64 + sjj * 8);     \
        cp16(_a + asto1, g_ao + abase + (srow + 64) * 256 + (c_) * 64 + sjj * 8); \
        unsigned _bB = _a + A_BYTES;                                           \
        _Pragma("unroll")                                                      \
        for (int _i = 0; _i < 4; ++_i) {                                       \
            int _n = srow + _i * 64;                                           \
            cp16(_bB + _n * 144 + sjj * 16, wh + _n * 256 + (c_) * 64 + sjj * 8); \
        }                                                                      \
        cp_commit();                                                           \
    } while (0)

    STAGE(0, 0);
    STAGE(1, 1);

    float acc[2][8][4];
#pragma unroll
    for (int mt = 0; mt < 2; ++mt)
#pragma unroll
        for (int nt = 0; nt < 8; ++nt)
#pragma unroll
            for (int q = 0; q < 4; ++q) acc[mt][nt][q] = 0.0f;

#pragma unroll 1
    for (int c = 0; c < 4; ++c) {
        const int st = c % 3;
        if (c == 3) cp_wait<0>(); else cp_wait<1>();
        __syncthreads();
        if (c + 2 < 4) STAGE(c + 2, (c + 2) % 3);

        const unsigned* Xs = (const unsigned*)(smem + SM_BUF + st * STG_BYTES);
        const unsigned* Bs = Xs + (A_BYTES >> 2);
#pragma unroll
        for (int ks = 0; ks < 4; ++ks) {
            unsigned a[2][4];
#pragma unroll
            for (int mt = 0; mt < 2; ++mt) {
                const unsigned* ar = Xs + (mw * 32 + mt * 16 + g) * 36 + ks * 8 + t;
                a[mt][0] = ar[0];
                a[mt][1] = ar[8 * 36];
                a[mt][2] = ar[4];
                a[mt][3] = ar[8 * 36 + 4];
            }
            unsigned bf[8][2];
#pragma unroll
            for (int nt = 0; nt < 8; ++nt) {
                const unsigned* br = Bs + (nq * 64 + nt * 8 + g) * 36 + ks * 8 + t;
                bf[nt][0] = br[0];
                bf[nt][1] = br[4];
            }
#pragma unroll
            for (int mt = 0; mt < 2; ++mt)
#pragma unroll
                for (int nt = 0; nt < 8; ++nt)
                    mma16(acc[mt][nt], a[mt], bf[nt]);
        }
        __syncthreads();
    }
#undef STAGE

    float2 bb[8];
#pragma unroll
    for (int nt = 0; nt < 8; ++nt)
        bb[nt] = *(float2*)(bias_s + nq * 64 + nt * 8 + 2 * t);

#pragma unroll
    for (int mt = 0; mt < 2; ++mt)
#pragma unroll
        for (int rh = 0; rh < 2; ++rh)
#pragma unroll
            for (int nt = 0; nt < 8; ++nt) {
                int n   = mw * 32 + mt * 16 + rh * 8 + g;
                int wv  = bw * 2 + (n >> 6);
                int tok = n & 63;
                int b   = wv >> 6, wy = (wv >> 3) & 7, wx = wv & 7;
                int y   = ((wy << 3) + (tok >> 3) + 4) & 63;
                int xc  = ((wx << 3) + (tok & 7) + 4) & 63;
                int col = nq * 64 + nt * 8 + 2 * t;
                *(float2*)(out + (((b << 6) | y) << 14) + (xc << 8) + col) =
                    make_float2(acc[mt][nt][rh * 2] + bb[nt].x,
                                acc[mt][nt][rh * 2 + 1] + bb[nt].y);
            }
}

// ============================================================
extern "C" void kernel_launch(void* const* d_in, const int* in_sizes, int n_in,
                              void* d_out, int out_size)
{
    const float* x  = (const float*)d_in[0];
    const float* Wq = (const float*)d_in[1];
    const float* bq = (const float*)d_in[2];
    const float* Wk = (const float*)d_in[3];
    const float* bk = (const float*)d_in[4];
    const float* Wv = (const float*)d_in[5];
    const float* bv = (const float*)d_in[6];
    const float* Wo = (const float*)d_in[7];
    const float* bo = (const float*)d_in[8];
    const float* ls = (const float*)d_in[9];
    const float* w1 = (const float*)d_in[10];
    const float* b1 = (const float*)d_in[11];
    const float* w2 = (const float*)d_in[12];
    float* out = (float*)d_out;

    cudaFuncSetAttribute(swin_qkv_kernel,
                         cudaFuncAttributeMaxDynamicSharedMemorySize, G_SMEM);
    cudaFuncSetAttribute(swin_proj_kernel,
                         cudaFuncAttributeMaxDynamicSharedMemorySize, G_SMEM);

    swin_bias_kernel<<<225, 512>>>(ls, w1, b1, w2);
    swin_cvt_kernel<<<16640, 256>>>(x, Wq, Wk, Wv, Wo);
    swin_qkv_kernel<<<512, 512, G_SMEM>>>(bq, bk, bv);
    swin_attn_kernel<<<dim3(NWIN, NHEAD), 128>>>();
    swin_proj_kernel<<<512, 512, G_SMEM>>>(bo, out);
}